// round 2
// baseline (speedup 1.0000x reference)
#include <cuda_runtime.h>

// Problem constants
constexpr int NB   = 32;     // batch
constexpr int T    = 1024;   // timesteps
constexpr int NI   = 512;    // input neurons
constexpr int NH   = 2048;   // hidden neurons
constexpr int NO   = 256;    // output neurons

constexpr int TC = 128;      // t-chunk per mainloop iteration
constexpr int KC = 32;       // k-chunk

// Fused layer kernel:  cur = W @ X + bias  (per batch, all T), then CUBA-LIF
// scan over t with reset-to-zero, writing binary spikes S.
//   W: [Oall, KTOT] row-major
//   X: [NB, KTOT, T]   (t contiguous)
//   S: [NB, Oall, T]
// CTA handles (o-tile of OT, one batch b, full T). blockDim = 256.
// Thread micro-tile: o in {h*64 + ty*4 + i}, t in {tx*4+j, 64+tx*4+j}.
template<int OT, int KTOT>
__global__ void __launch_bounds__(256)
snn_layer_kernel(const float* __restrict__ W,
                 const float* __restrict__ bias,
                 const float* __restrict__ X,
                 float* __restrict__ S,
                 int Oall)
{
    extern __shared__ float smem[];
    float* sA = smem;                          // [KC][OT+4]  (k-major W tile)
    float* sB = sA + KC * (OT + 4);            // [KC][TC+4]  (k-major X tile)
    float* sC = sB + KC * (TC + 4);            // [OT][TC+1]  (cur / spikes)

    constexpr int SAW = OT + 4;
    constexpr int SBW = TC + 4;
    constexpr int SCW = TC + 1;                // odd stride: conflict-free scan
    constexpr int NFO = OT / 64;               // o-fragments (2 for OT=128, 1 for OT=64)

    const int ot  = blockIdx.x;
    const int b   = blockIdx.y;
    const int o0  = ot * OT;
    const int tid = threadIdx.x;
    const int tx  = tid & 15;
    const int ty  = tid >> 4;

    const float* Wb = W + (size_t)o0 * KTOT;
    const float* Xb = X + (size_t)b * KTOT * T;
    float*       Sb = S + ((size_t)b * Oall + o0) * T;

    // LIF state (one neuron per thread for tid < OT)
    float v  = 0.0f;
    float bi = (tid < OT) ? bias[o0 + tid] : 0.0f;

    float acc[NFO * 4][8];

    for (int t0 = 0; t0 < T; t0 += TC) {
        #pragma unroll
        for (int i = 0; i < NFO * 4; i++)
            #pragma unroll
            for (int j = 0; j < 8; j++) acc[i][j] = 0.0f;

        for (int k0 = 0; k0 < KTOT; k0 += KC) {
            __syncthreads();
            // ---- stage W tile (transpose to k-major) ----
            {
                constexpr int TOT4 = OT * KC / 4;   // float4 elements
                #pragma unroll
                for (int p = 0; p < TOT4 / 256; p++) {
                    int idx = tid + p * 256;
                    int row = idx / (KC / 4);       // o within tile
                    int c4  = idx % (KC / 4);       // k/4 within chunk
                    float4 w = *reinterpret_cast<const float4*>(
                        Wb + (size_t)row * KTOT + k0 + c4 * 4);
                    sA[(c4 * 4 + 0) * SAW + row] = w.x;
                    sA[(c4 * 4 + 1) * SAW + row] = w.y;
                    sA[(c4 * 4 + 2) * SAW + row] = w.z;
                    sA[(c4 * 4 + 3) * SAW + row] = w.w;
                }
            }
            // ---- stage X tile (already k-major, t contiguous) ----
            {
                constexpr int TOT4 = KC * TC / 4;
                #pragma unroll
                for (int p = 0; p < TOT4 / 256; p++) {
                    int idx = tid + p * 256;
                    int row = idx / (TC / 4);       // k within chunk
                    int c4  = idx % (TC / 4);       // t/4
                    float4 xv = *reinterpret_cast<const float4*>(
                        Xb + (size_t)(k0 + row) * T + t0 + c4 * 4);
                    *reinterpret_cast<float4*>(&sB[row * SBW + c4 * 4]) = xv;
                }
            }
            __syncthreads();
            // ---- compute ----
            #pragma unroll
            for (int k = 0; k < KC; k++) {
                float afrag[NFO * 4];
                float bfrag[8];
                #pragma unroll
                for (int h = 0; h < NFO; h++) {
                    float4 av = *reinterpret_cast<const float4*>(
                        &sA[k * SAW + h * 64 + ty * 4]);
                    afrag[h * 4 + 0] = av.x; afrag[h * 4 + 1] = av.y;
                    afrag[h * 4 + 2] = av.z; afrag[h * 4 + 3] = av.w;
                }
                float4 b0 = *reinterpret_cast<const float4*>(&sB[k * SBW + tx * 4]);
                float4 b1 = *reinterpret_cast<const float4*>(&sB[k * SBW + 64 + tx * 4]);
                bfrag[0] = b0.x; bfrag[1] = b0.y; bfrag[2] = b0.z; bfrag[3] = b0.w;
                bfrag[4] = b1.x; bfrag[5] = b1.y; bfrag[6] = b1.z; bfrag[7] = b1.w;
                #pragma unroll
                for (int i = 0; i < NFO * 4; i++)
                    #pragma unroll
                    for (int j = 0; j < 8; j++)
                        acc[i][j] = fmaf(afrag[i], bfrag[j], acc[i][j]);
            }
        }

        // ---- epilogue: acc -> sC (cur) ----
        __syncthreads();
        #pragma unroll
        for (int h = 0; h < NFO; h++)
            #pragma unroll
            for (int i = 0; i < 4; i++) {
                int o = h * 64 + ty * 4 + i;
                #pragma unroll
                for (int j = 0; j < 8; j++) {
                    int t = (j < 4) ? (tx * 4 + j) : (64 + tx * 4 + (j - 4));
                    sC[o * SCW + t] = acc[h * 4 + i][j];
                }
            }
        __syncthreads();

        // ---- LIF scan over this t-chunk (thread tid owns neuron o0+tid) ----
        if (tid < OT) {
            float vloc = v;
            #pragma unroll 8
            for (int tt = 0; tt < TC; tt++) {
                float c = sC[tid * SCW + tt] + bi;
                vloc = fmaf(vloc, 0.95f, c);
                bool fire = (vloc >= 1.0f);
                sC[tid * SCW + tt] = fire ? 1.0f : 0.0f;
                vloc = fire ? 0.0f : vloc;
            }
            v = vloc;
        }
        __syncthreads();

        // ---- coalesced spike store ----
        for (int idx = tid; idx < OT * TC; idx += 256) {
            int row = idx / TC;
            int tt  = idx % TC;
            Sb[(size_t)row * T + t0 + tt] = sC[row * SCW + tt];
        }
        // next iteration's first __syncthreads() protects sC reuse
    }
}

extern "C" void kernel_launch(void* const* d_in, const int* in_sizes, int n_in,
                              void* d_out, int out_size)
{
    const float* x  = (const float*)d_in[0];   // [32, 512, 1024]
    const float* w1 = (const float*)d_in[1];   // [2048, 512]
    const float* b1 = (const float*)d_in[2];   // [2048]
    const float* w2 = (const float*)d_in[3];   // [256, 2048]
    const float* b2 = (const float*)d_in[4];   // [256]

    float* spk1 = (float*)d_out;                          // [32, 2048, 1024]
    float* spk2 = spk1 + (size_t)NB * NH * T;             // [32, 256, 1024]

    const int smem1 = (KC * (128 + 4) + KC * (TC + 4) + 128 * (TC + 1)) * (int)sizeof(float);
    const int smem2 = (KC * (64 + 4)  + KC * (TC + 4) + 64  * (TC + 1)) * (int)sizeof(float);

    cudaFuncSetAttribute(snn_layer_kernel<128, NI>,
                         cudaFuncAttributeMaxDynamicSharedMemorySize, smem1);
    cudaFuncSetAttribute(snn_layer_kernel<64, NH>,
                         cudaFuncAttributeMaxDynamicSharedMemorySize, smem2);

    // Layer 1: cur1 = w1 @ x + b1, LIF -> spk1
    snn_layer_kernel<128, NI><<<dim3(NH / 128, NB), 256, smem1>>>(w1, b1, x, spk1, NH);
    // Layer 2: cur2 = w2 @ spk1 + b2, LIF -> spk2
    snn_layer_kernel<64, NH><<<dim3(NO / 64, NB), 256, smem2>>>(w2, b2, spk1, spk2, NO);
}

// round 9
// speedup vs baseline: 1.5771x; 1.5771x over previous
#include <cuda_runtime.h>
#include <cstdint>

// ---------------- problem constants ----------------
constexpr int NB = 32, T = 1024, NI = 512, NH = 2048, NO = 256;

// ---------------- tile constants -------------------
constexpr int OTILE = 128;   // o per CTA
constexpr int TTILE = 128;   // t per chunk
constexpr int KC    = 32;    // k per stage
constexpr int SAW   = 132;   // sA row stride (floats), 16B-aligned rows
constexpr int SBW   = 132;   // sB row stride
constexpr int STAGE_FLOATS = KC * SAW + KC * SBW;       // 8448
constexpr int STAGE_BYTES  = STAGE_FLOATS * 4;          // 33792
constexpr int CS    = 130;   // sC row stride (floats), even -> 8B aligned rows
constexpr int SMEM_BYTES = 2 * STAGE_BYTES;             // 67584 ; sC (66560B) aliases

// ---------------- device scratch (no cudaMalloc) ----------------
__device__ __align__(256) float g_w1T [(size_t)NI * NH];   // [NI][NH]
__device__ __align__(256) float g_w2T [(size_t)NH * NO];   // [NH][NO]
__device__ __align__(256) float g_cur2[(size_t)NB * NO * T];

// ---------------- PTX helpers ----------------
__device__ __forceinline__ uint32_t smem_u32(const void* p) {
    uint32_t a;
    asm("{ .reg .u64 t; cvta.to.shared.u64 t, %1; cvt.u32.u64 %0, t; }" : "=r"(a) : "l"(p));
    return a;
}
__device__ __forceinline__ void cp16(uint32_t dst, const void* src) {
    asm volatile("cp.async.cg.shared.global [%0], [%1], 16;" :: "r"(dst), "l"(src));
}
#define CP_COMMIT() asm volatile("cp.async.commit_group;" ::: "memory")
#define CP_WAIT(n)  asm volatile("cp.async.wait_group %0;" :: "n"(n) : "memory")

// packed dual fp32 FMA: each 32-bit half is an independent IEEE RN fmaf
__device__ __forceinline__ void ffma2(unsigned long long& d,
                                      unsigned long long a, unsigned long long b) {
    asm("fma.rn.f32x2 %0, %1, %2, %0;" : "+l"(d) : "l"(a), "l"(b));
}
__device__ __forceinline__ unsigned long long splat2(float x) {
    unsigned long long r;
    asm("mov.b64 %0, {%1, %1};" : "=l"(r) : "f"(x));
    return r;
}
__device__ __forceinline__ void unpack2(float& lo, float& hi, unsigned long long v) {
    asm("mov.b64 {%0, %1}, %2;" : "=f"(lo), "=f"(hi) : "l"(v));
}
__device__ __forceinline__ void lds_v2u64(unsigned long long& x, unsigned long long& y,
                                          uint32_t addr) {
    asm volatile("ld.shared.v2.b64 {%0, %1}, [%2];" : "=l"(x), "=l"(y) : "r"(addr));
}

// ---------------- weight transpose: W[O][K] -> WT[K][O] ----------------
__global__ void k_wT(const float* __restrict__ W, float* __restrict__ WT, int O, int K) {
    __shared__ float t[32][33];
    int o0 = blockIdx.x * 32, k0 = blockIdx.y * 32;
    int tx = threadIdx.x, ty = threadIdx.y;
    #pragma unroll
    for (int i = 0; i < 32; i += 8)
        t[ty + i][tx] = W[(size_t)(o0 + ty + i) * K + k0 + tx];
    __syncthreads();
    #pragma unroll
    for (int i = 0; i < 32; i += 8)
        WT[(size_t)(k0 + ty + i) * O + o0 + tx] = t[tx][ty + i];
}

// ---------------- GEMM (f32x2 FFMA, exact sequential-k order) + optional LIF ----------------
// cur[o,t] = sum_k WT[k][o] * X[b][k][t]   (single fp32 fmaf chain per element,
// k ascending -> bitwise identical to the reference-matching R1 kernel)
template<int KTOT, int NCHUNK, bool FUSE>
__global__ void __launch_bounds__(256, 2)
snn_gemm(const float* __restrict__ WT,    // [KTOT][Oall]
         const float* __restrict__ bias,  // [Oall] (FUSE only)
         const float* __restrict__ X,     // [NB][KTOT][T]
         float*       __restrict__ OUT,   // [NB][Oall][T] (spikes if FUSE, else cur)
         int Oall)
{
    constexpr int NKC = KTOT / KC;
    extern __shared__ float smem[];
    const uint32_t sb = smem_u32(smem);
    float* sC = smem;                       // aliases stage buffers (disjoint in time)

    const int tid = threadIdx.x;
    const int tx  = tid & 15;
    const int ty  = tid >> 4;
    const int o0  = blockIdx.x * OTILE;
    const int b   = blockIdx.y;

    const float* Xb = X + (size_t)b * KTOT * T;

    // LIF state (FUSE): thread tid<128 owns neuron o0+tid
    float v  = 0.0f;
    const float bi = (FUSE && tid < OTILE) ? bias[o0 + tid] : 0.0f;

    // per-lane smem addr components
    const uint32_t aOff0 = (uint32_t)(ty * 16);          // col ty*4 (bytes)
    const uint32_t aOff1 = (uint32_t)(256 + ty * 16);    // col 64+ty*4
    const uint32_t bOff0 = (uint32_t)(tx * 16);
    const uint32_t bOff1 = (uint32_t)(256 + tx * 16);

    unsigned long long acc[32];   // [op 0..3][j 0..7] ; lo half = even o of pair

    for (int tc = 0; tc < NCHUNK; tc++) {
        const int t0 = (NCHUNK == 1 ? (int)blockIdx.z : tc) * TTILE;

        #pragma unroll
        for (int i = 0; i < 32; i++) acc[i] = 0ull;

        // ---------- stage loader (cp.async, 16B) ----------
        auto load_stage = [&](int s, int kc) {
            const int k0 = kc * KC;
            const uint32_t base = sb + (uint32_t)s * STAGE_BYTES;
            #pragma unroll
            for (int p = 0; p < 4; p++) {          // A: 32 rows x 32 float4
                int i = tid + p * 256;
                int r = i >> 5, c = i & 31;
                cp16(base + (uint32_t)(r * SAW * 4 + c * 16),
                     WT + (size_t)(k0 + r) * Oall + o0 + c * 4);
            }
            #pragma unroll
            for (int p = 0; p < 4; p++) {          // B: 32 rows x 32 float4
                int i = tid + p * 256;
                int r = i >> 5, c = i & 31;
                cp16(base + (uint32_t)(KC * SAW * 4 + r * SBW * 4 + c * 16),
                     Xb + (size_t)(k0 + r) * T + t0 + c * 4);
            }
        };

        load_stage(0, 0); CP_COMMIT();

        for (int kc = 0; kc < NKC; kc++) {
            const int s = kc & 1;
            if (kc + 1 < NKC) { load_stage(1 - s, kc + 1); CP_COMMIT(); CP_WAIT(1); }
            else              { CP_WAIT(0); }
            __syncthreads();

            const uint32_t aBase = sb + (uint32_t)s * STAGE_BYTES;
            const uint32_t bBase = aBase + (uint32_t)(KC * SAW * 4);

            #pragma unroll 8
            for (int k = 0; k < KC; k++) {
                const uint32_t aRow = aBase + (uint32_t)(k * SAW * 4);
                const uint32_t bRow = bBase + (uint32_t)(k * SBW * 4);
                unsigned long long a2[4];
                lds_v2u64(a2[0], a2[1], aRow + aOff0);   // o pairs (ty*4+0,1),(2,3)
                lds_v2u64(a2[2], a2[3], aRow + aOff1);   // (64+ty*4+0,1),(2,3)
                float4 b0, b1;
                asm volatile("ld.shared.v4.f32 {%0,%1,%2,%3}, [%4];"
                    : "=f"(b0.x), "=f"(b0.y), "=f"(b0.z), "=f"(b0.w) : "r"(bRow + bOff0));
                asm volatile("ld.shared.v4.f32 {%0,%1,%2,%3}, [%4];"
                    : "=f"(b1.x), "=f"(b1.y), "=f"(b1.z), "=f"(b1.w) : "r"(bRow + bOff1));
                unsigned long long bs[8];
                bs[0] = splat2(b0.x); bs[1] = splat2(b0.y);
                bs[2] = splat2(b0.z); bs[3] = splat2(b0.w);
                bs[4] = splat2(b1.x); bs[5] = splat2(b1.y);
                bs[6] = splat2(b1.z); bs[7] = splat2(b1.w);
                #pragma unroll
                for (int op = 0; op < 4; op++)
                    #pragma unroll
                    for (int j = 0; j < 8; j++)
                        ffma2(acc[op * 8 + j], a2[op], bs[j]);
            }
            __syncthreads();   // protect stage s before it's reloaded next iter
        }

        // ---------- epilogue: acc -> sC (aliases stages; all cp.async drained) ----------
        #pragma unroll
        for (int op = 0; op < 4; op++) {
            const int o_lo = (op < 2) ? (ty * 4 + op * 2) : (64 + ty * 4 + (op - 2) * 2);
            #pragma unroll
            for (int j = 0; j < 8; j++) {
                const int t = (j < 4) ? (tx * 4 + j) : (64 + tx * 4 + (j - 4));
                float lo, hi;
                unpack2(lo, hi, acc[op * 8 + j]);
                sC[o_lo * CS + t]       = lo;
                sC[(o_lo + 1) * CS + t] = hi;
            }
        }
        __syncthreads();

        if (FUSE) {
            // LIF scan (ops identical to R1): thread tid<128 owns its neuron row
            if (tid < OTILE) {
                float vloc = v;
                #pragma unroll 8
                for (int t = 0; t < TTILE; t++) {
                    float c = sC[tid * CS + t] + bi;
                    vloc = fmaf(vloc, 0.95f, c);
                    bool f = (vloc >= 1.0f);
                    sC[tid * CS + t] = f ? 1.0f : 0.0f;
                    vloc = f ? 0.0f : vloc;
                }
                v = vloc;
            }
            __syncthreads();
        }

        // ---------- coalesced store-out (float2; sC rows 8B-aligned) ----------
        #pragma unroll
        for (int p = 0; p < 32; p++) {
            int i = tid + p * 256;
            int r = i >> 6, c = i & 63;
            float2 val = *reinterpret_cast<const float2*>(sC + r * CS + c * 2);
            *reinterpret_cast<float2*>(OUT + (size_t)(b * Oall + o0 + r) * T + t0 + c * 2) = val;
        }
        __syncthreads();   // sC region becomes stage buffers again next chunk
    }
}

// ---------------- layer-2 LIF scan (ops identical to R1) ----------------
__global__ void k_lif2(const float* __restrict__ cur2, const float* __restrict__ b2,
                       float* __restrict__ spk2) {
    int idx = blockIdx.x * 256 + threadIdx.x;       // 0..NB*NO-1
    int b = idx >> 8, o = idx & (NO - 1);
    const float4* src = reinterpret_cast<const float4*>(cur2 + (size_t)(b * NO + o) * T);
    float4* dst = reinterpret_cast<float4*>(spk2 + (size_t)(b * NO + o) * T);
    float bi = b2[o], v = 0.0f;
    for (int q = 0; q < T / 4; q++) {
        float4 cf = src[q];
        float cv[4] = {cf.x, cf.y, cf.z, cf.w};
        float s[4];
        #pragma unroll
        for (int j = 0; j < 4; j++) {
            float c = cv[j] + bi;
            v = fmaf(v, 0.95f, c);
            bool f = (v >= 1.0f);
            s[j] = f ? 1.0f : 0.0f;
            v = f ? 0.0f : v;
        }
        dst[q] = make_float4(s[0], s[1], s[2], s[3]);
    }
}

// ---------------- host launcher ----------------
extern "C" void kernel_launch(void* const* d_in, const int* in_sizes, int n_in,
                              void* d_out, int out_size)
{
    const float* x  = (const float*)d_in[0];   // [32,512,1024]
    const float* w1 = (const float*)d_in[1];   // [2048,512]
    const float* b1 = (const float*)d_in[2];
    const float* w2 = (const float*)d_in[3];   // [256,2048]
    const float* b2 = (const float*)d_in[4];

    float* spk1 = (float*)d_out;                   // [32,2048,1024]
    float* spk2 = spk1 + (size_t)NB * NH * T;      // [32,256,1024]

    void *w1T, *w2T, *cur2;
    cudaGetSymbolAddress(&w1T,  g_w1T);
    cudaGetSymbolAddress(&w2T,  g_w2T);
    cudaGetSymbolAddress(&cur2, g_cur2);

    cudaFuncSetAttribute(snn_gemm<NI, 8, true>,
                         cudaFuncAttributeMaxDynamicSharedMemorySize, SMEM_BYTES);
    cudaFuncSetAttribute(snn_gemm<NH, 1, false>,
                         cudaFuncAttributeMaxDynamicSharedMemorySize, SMEM_BYTES);

    // prep: weight transposes (k-major for 16B cp.async staging)
    k_wT<<<dim3(NH / 32, NI / 32), dim3(32, 8)>>>(w1, (float*)w1T, NH, NI);
    k_wT<<<dim3(NO / 32, NH / 32), dim3(32, 8)>>>(w2, (float*)w2T, NO, NH);

    // layer 1 fused GEMM+LIF: 16 x 32 = 512 CTAs, spk1 -> d_out
    snn_gemm<NI, 8, true><<<dim3(NH / OTILE, NB), 256, SMEM_BYTES>>>(
        (const float*)w1T, b1, x, spk1, NH);

    // layer 2 GEMM unfused over t-chunks: 2 x 32 x 8 = 512 CTAs, cur2 -> scratch
    snn_gemm<NH, 1, false><<<dim3(NO / OTILE, NB, T / TTILE), 256, SMEM_BYTES>>>(
        (const float*)w2T, nullptr, spk1, (float*)cur2, NO);

    // layer 2 LIF scan
    k_lif2<<<NB * NO / 256, 256>>>((const float*)cur2, b2, spk2);
}